// round 1
// baseline (speedup 1.0000x reference)
#include <cuda_runtime.h>

// Deterministic two-pass reduction.
// Pass 1: grid-stride over float4 chunks, per-block partial sums into a
//         __device__ global scratch array (no allocations allowed).
// Pass 2: single block reduces the partials into d_out[0].

static constexpr int BLOCKS  = 148 * 8;   // 1184 CTAs, 8 per SM
static constexpr int THREADS = 256;

__device__ float g_partials[BLOCKS];

__global__ __launch_bounds__(THREADS) void trajloss_partial_kernel(
    const float* __restrict__ pred,   // N+1 elements
    const float* __restrict__ xs,     // N elements
    const float* __restrict__ ys,     // N elements
    int n4)                           // N / 4
{
    const float4* __restrict__ pred4 = reinterpret_cast<const float4*>(pred);
    const float4* __restrict__ x4    = reinterpret_cast<const float4*>(xs);
    const float4* __restrict__ y4    = reinterpret_cast<const float4*>(ys);

    float acc = 0.0f;

    int idx    = blockIdx.x * THREADS + threadIdx.x;
    int stride = BLOCKS * THREADS;

    for (int i = idx; i < n4; i += stride) {
        float4 p  = pred4[i];
        float4 xv = x4[i];
        float4 yv = y4[i];
        float  p4 = pred[i * 4 + 4];   // one extra scalar; L1/L2-resident

        float dx0 = xv.x - p.x;
        float dx1 = xv.y - p.y;
        float dx2 = xv.z - p.z;
        float dx3 = xv.w - p.w;

        float dy0 = yv.x - p.y;
        float dy1 = yv.y - p.z;
        float dy2 = yv.z - p.w;
        float dy3 = yv.w - p4;

        acc = fmaf(dx0, dx0, acc);
        acc = fmaf(dy0, dy0, acc);
        acc = fmaf(dx1, dx1, acc);
        acc = fmaf(dy1, dy1, acc);
        acc = fmaf(dx2, dx2, acc);
        acc = fmaf(dy2, dy2, acc);
        acc = fmaf(dx3, dx3, acc);
        acc = fmaf(dy3, dy3, acc);
    }

    // warp reduce
    #pragma unroll
    for (int off = 16; off > 0; off >>= 1)
        acc += __shfl_xor_sync(0xFFFFFFFFu, acc, off);

    // block reduce via smem
    __shared__ float warp_sums[THREADS / 32];
    int lane = threadIdx.x & 31;
    int wid  = threadIdx.x >> 5;
    if (lane == 0) warp_sums[wid] = acc;
    __syncthreads();

    if (wid == 0) {
        float v = (lane < THREADS / 32) ? warp_sums[lane] : 0.0f;
        #pragma unroll
        for (int off = 4; off > 0; off >>= 1)
            v += __shfl_xor_sync(0xFFFFFFFFu, v, off);
        if (lane == 0) g_partials[blockIdx.x] = v;
    }
}

__global__ __launch_bounds__(1024) void trajloss_final_kernel(float* __restrict__ out)
{
    float acc = 0.0f;
    for (int i = threadIdx.x; i < BLOCKS; i += 1024)
        acc += g_partials[i];

    #pragma unroll
    for (int off = 16; off > 0; off >>= 1)
        acc += __shfl_xor_sync(0xFFFFFFFFu, acc, off);

    __shared__ float warp_sums[32];
    int lane = threadIdx.x & 31;
    int wid  = threadIdx.x >> 5;
    if (lane == 0) warp_sums[wid] = acc;
    __syncthreads();

    if (wid == 0) {
        float v = (lane < 32) ? warp_sums[lane] : 0.0f;
        #pragma unroll
        for (int off = 16; off > 0; off >>= 1)
            v += __shfl_xor_sync(0xFFFFFFFFu, v, off);
        if (lane == 0) out[0] = v;
    }
}

extern "C" void kernel_launch(void* const* d_in, const int* in_sizes, int n_in,
                              void* d_out, int out_size)
{
    const float* pred = (const float*)d_in[0];   // N+1
    const float* xs   = (const float*)d_in[1];   // N
    const float* ys   = (const float*)d_in[2];   // N
    float* out        = (float*)d_out;

    int n  = in_sizes[1];       // N
    int n4 = n >> 2;            // N divisible by 4 (16777216)

    trajloss_partial_kernel<<<BLOCKS, THREADS>>>(pred, xs, ys, n4);
    trajloss_final_kernel<<<1, 1024>>>(out);
}

// round 2
// speedup vs baseline: 1.1142x; 1.1142x over previous
#include <cuda_runtime.h>

// Single-kernel deterministic reduction using the "last block finishes" pattern.
// - Each block computes a partial sum into a __device__ global array.
// - __threadfence + atomic counter; the last arriving block reduces the
//   partials into d_out[0] and resets the counter to 0 (graph-replay safe:
//   counter is 0 at entry and 0 at exit of every call, partials are fully
//   overwritten, final summation order is a fixed loop -> deterministic).

static constexpr int BLOCKS  = 148 * 8;   // 1184 CTAs
static constexpr int THREADS = 256;

__device__ float        g_partials[BLOCKS];
__device__ unsigned int g_done_count;      // zero-init at module load

__global__ __launch_bounds__(THREADS) void trajloss_fused_kernel(
    const float* __restrict__ pred,   // N+1 elements
    const float* __restrict__ xs,     // N elements
    const float* __restrict__ ys,     // N elements
    float* __restrict__ out,
    int n4)                           // N / 4
{
    const float4* __restrict__ pred4 = reinterpret_cast<const float4*>(pred);
    const float4* __restrict__ x4    = reinterpret_cast<const float4*>(xs);
    const float4* __restrict__ y4    = reinterpret_cast<const float4*>(ys);

    float acc = 0.0f;

    int idx    = blockIdx.x * THREADS + threadIdx.x;
    int stride = BLOCKS * THREADS;

    #pragma unroll 4
    for (int i = idx; i < n4; i += stride) {
        float4 p  = __ldcs(&pred4[i]);
        float4 xv = __ldcs(&x4[i]);
        float4 yv = __ldcs(&y4[i]);
        float  p4 = __ldg(&pred[i * 4 + 4]);   // L1-resident (neighbor's line)

        float dx0 = xv.x - p.x;
        float dx1 = xv.y - p.y;
        float dx2 = xv.z - p.z;
        float dx3 = xv.w - p.w;

        float dy0 = yv.x - p.y;
        float dy1 = yv.y - p.z;
        float dy2 = yv.z - p.w;
        float dy3 = yv.w - p4;

        acc = fmaf(dx0, dx0, acc);
        acc = fmaf(dy0, dy0, acc);
        acc = fmaf(dx1, dx1, acc);
        acc = fmaf(dy1, dy1, acc);
        acc = fmaf(dx2, dx2, acc);
        acc = fmaf(dy2, dy2, acc);
        acc = fmaf(dx3, dx3, acc);
        acc = fmaf(dy3, dy3, acc);
    }

    // ---- intra-block reduction ----
    #pragma unroll
    for (int off = 16; off > 0; off >>= 1)
        acc += __shfl_xor_sync(0xFFFFFFFFu, acc, off);

    __shared__ float warp_sums[THREADS / 32];
    __shared__ bool  is_last;
    int lane = threadIdx.x & 31;
    int wid  = threadIdx.x >> 5;
    if (lane == 0) warp_sums[wid] = acc;
    __syncthreads();

    if (wid == 0) {
        float v = (lane < THREADS / 32) ? warp_sums[lane] : 0.0f;
        #pragma unroll
        for (int off = 4; off > 0; off >>= 1)
            v += __shfl_xor_sync(0xFFFFFFFFu, v, off);
        if (lane == 0) {
            g_partials[blockIdx.x] = v;
            __threadfence();
            unsigned int prev = atomicAdd(&g_done_count, 1u);
            is_last = (prev == (unsigned int)(BLOCKS - 1));
        }
    }
    __syncthreads();

    // ---- last block reduces all partials ----
    if (is_last) {
        float t = 0.0f;
        for (int i = threadIdx.x; i < BLOCKS; i += THREADS)
            t += g_partials[i];

        #pragma unroll
        for (int off = 16; off > 0; off >>= 1)
            t += __shfl_xor_sync(0xFFFFFFFFu, t, off);

        if (lane == 0) warp_sums[wid] = t;
        __syncthreads();

        if (wid == 0) {
            float v = (lane < THREADS / 32) ? warp_sums[lane] : 0.0f;
            #pragma unroll
            for (int off = 4; off > 0; off >>= 1)
                v += __shfl_xor_sync(0xFFFFFFFFu, v, off);
            if (lane == 0) {
                out[0] = v;
                g_done_count = 0;     // reset for next (graph-replayed) call
            }
        }
    }
}

extern "C" void kernel_launch(void* const* d_in, const int* in_sizes, int n_in,
                              void* d_out, int out_size)
{
    const float* pred = (const float*)d_in[0];   // N+1
    const float* xs   = (const float*)d_in[1];   // N
    const float* ys   = (const float*)d_in[2];   // N
    float* out        = (float*)d_out;

    int n  = in_sizes[1];
    int n4 = n >> 2;

    trajloss_fused_kernel<<<BLOCKS, THREADS>>>(pred, xs, ys, out, n4);
}